// round 1
// baseline (speedup 1.0000x reference)
#include <cuda_runtime.h>
#include <math.h>

// Problem constants (fixed by setup_inputs)
#define D_MODEL 512
#define NUM_HEADS 8
#define DK 64
#define BATCH 4
#define SEQ 8192
#define M_TOTAL (BATCH * SEQ)          // 32768 rows
#define BH (BATCH * NUM_HEADS)         // 32

// ---------------- scratch (static device arrays; no runtime allocation) ----
__device__ float g_phi_q[M_TOTAL * D_MODEL];   // phi(q proj)  [B,S,H*dk]
__device__ float g_phi_k[M_TOTAL * D_MODEL];   // phi(k proj)
__device__ float g_vp[M_TOTAL * D_MODEL];      // v proj
__device__ float g_attn[M_TOTAL * D_MODEL];    // attention out, [B,S,H*dk]
__device__ float g_kv[BH * DK * DK];           // per (b,h): [d][e]
__device__ float g_ksum[BH * DK];

// ---------------------------------------------------------------------------
// Fused gated projection GEMM:
//   a1 = x @ w1^T + b1 ; a2 = x @ w2^T + b2 ; p = silu(a1)*a2
//   z=0 (q), z=1 (k): out = elu(p)+1 ; z=2 (v): out = p
// Tile: BM=64, BN=64, BK=16, 256 threads, 4x4 register tile, dual accumulators.
// ---------------------------------------------------------------------------
__global__ __launch_bounds__(256)
void proj_gemm(const float* __restrict__ xq, const float* __restrict__ xk,
               const float* __restrict__ xv,
               const float* __restrict__ qw1, const float* __restrict__ qw2,
               const float* __restrict__ kw1, const float* __restrict__ kw2,
               const float* __restrict__ vw1, const float* __restrict__ vw2,
               const float* __restrict__ qb1, const float* __restrict__ qb2,
               const float* __restrict__ kb1, const float* __restrict__ kb2,
               const float* __restrict__ vb1, const float* __restrict__ vb2)
{
    const int z = blockIdx.z;
    const float* x  = (z == 0) ? xq  : (z == 1) ? xk  : xv;
    const float* w1 = (z == 0) ? qw1 : (z == 1) ? kw1 : vw1;
    const float* w2 = (z == 0) ? qw2 : (z == 1) ? kw2 : vw2;
    const float* b1 = (z == 0) ? qb1 : (z == 1) ? kb1 : vb1;
    const float* b2 = (z == 0) ? qb2 : (z == 1) ? kb2 : vb2;
    float* out      = (z == 0) ? g_phi_q : (z == 1) ? g_phi_k : g_vp;
    const bool do_phi = (z < 2);

    __shared__ float As[16][64];
    __shared__ float W1s[16][64];
    __shared__ float W2s[16][64];

    const int tx = threadIdx.x;          // 0..15 -> N
    const int ty = threadIdx.y;          // 0..15 -> M
    const int t  = ty * 16 + tx;
    const int m0 = blockIdx.y * 64;
    const int n0 = blockIdx.x * 64;

    // loader mapping: each thread loads one float4 per tile
    const int lr = t >> 2;               // tile row 0..63
    const int lc = (t & 3) * 4;          // k offset 0,4,8,12

    float acc1[4][4] = {};
    float acc2[4][4] = {};

    const size_t xrow  = (size_t)(m0 + lr) * D_MODEL;
    const size_t wrow  = (size_t)(n0 + lr) * D_MODEL;

    for (int k0 = 0; k0 < D_MODEL; k0 += 16) {
        float4 a = *(const float4*)&x[xrow + k0 + lc];
        float4 u = *(const float4*)&w1[wrow + k0 + lc];
        float4 w = *(const float4*)&w2[wrow + k0 + lc];
        As[lc + 0][lr] = a.x; As[lc + 1][lr] = a.y; As[lc + 2][lr] = a.z; As[lc + 3][lr] = a.w;
        W1s[lc + 0][lr] = u.x; W1s[lc + 1][lr] = u.y; W1s[lc + 2][lr] = u.z; W1s[lc + 3][lr] = u.w;
        W2s[lc + 0][lr] = w.x; W2s[lc + 1][lr] = w.y; W2s[lc + 2][lr] = w.z; W2s[lc + 3][lr] = w.w;
        __syncthreads();

        #pragma unroll
        for (int k = 0; k < 16; k++) {
            float4 ra = *(float4*)&As[k][ty * 4];
            float4 r1 = *(float4*)&W1s[k][tx * 4];
            float4 r2 = *(float4*)&W2s[k][tx * 4];
            float av[4] = {ra.x, ra.y, ra.z, ra.w};
            float w1v[4] = {r1.x, r1.y, r1.z, r1.w};
            float w2v[4] = {r2.x, r2.y, r2.z, r2.w};
            #pragma unroll
            for (int i = 0; i < 4; i++) {
                #pragma unroll
                for (int j = 0; j < 4; j++) {
                    acc1[i][j] += av[i] * w1v[j];
                    acc2[i][j] += av[i] * w2v[j];
                }
            }
        }
        __syncthreads();
    }

    #pragma unroll
    for (int i = 0; i < 4; i++) {
        int m = m0 + ty * 4 + i;
        #pragma unroll
        for (int j = 0; j < 4; j++) {
            int n = n0 + tx * 4 + j;
            float a1 = acc1[i][j] + b1[n];
            float a2 = acc2[i][j] + b2[n];
            float s  = a1 / (1.0f + expf(-a1));   // silu
            float p  = s * a2;
            if (do_phi) p = (p > 0.0f) ? (p + 1.0f) : expf(p);  // elu(p)+1
            out[(size_t)m * D_MODEL + n] = p;
        }
    }
}

// ---------------------------------------------------------------------------
// Final projection GEMM: out = attn @ out_w^T + out_b  (writes d_out)
// ---------------------------------------------------------------------------
__global__ __launch_bounds__(256)
void final_gemm(const float* __restrict__ w, const float* __restrict__ b,
                float* __restrict__ out)
{
    __shared__ float As[16][64];
    __shared__ float Ws[16][64];

    const int tx = threadIdx.x, ty = threadIdx.y;
    const int t  = ty * 16 + tx;
    const int m0 = blockIdx.y * 64;
    const int n0 = blockIdx.x * 64;
    const int lr = t >> 2;
    const int lc = (t & 3) * 4;

    float acc[4][4] = {};

    const size_t xrow = (size_t)(m0 + lr) * D_MODEL;
    const size_t wrow = (size_t)(n0 + lr) * D_MODEL;

    for (int k0 = 0; k0 < D_MODEL; k0 += 16) {
        float4 a = *(const float4*)&g_attn[xrow + k0 + lc];
        float4 u = *(const float4*)&w[wrow + k0 + lc];
        As[lc + 0][lr] = a.x; As[lc + 1][lr] = a.y; As[lc + 2][lr] = a.z; As[lc + 3][lr] = a.w;
        Ws[lc + 0][lr] = u.x; Ws[lc + 1][lr] = u.y; Ws[lc + 2][lr] = u.z; Ws[lc + 3][lr] = u.w;
        __syncthreads();

        #pragma unroll
        for (int k = 0; k < 16; k++) {
            float4 ra = *(float4*)&As[k][ty * 4];
            float4 rw = *(float4*)&Ws[k][tx * 4];
            float av[4] = {ra.x, ra.y, ra.z, ra.w};
            float wv[4] = {rw.x, rw.y, rw.z, rw.w};
            #pragma unroll
            for (int i = 0; i < 4; i++)
                #pragma unroll
                for (int j = 0; j < 4; j++)
                    acc[i][j] += av[i] * wv[j];
        }
        __syncthreads();
    }

    #pragma unroll
    for (int i = 0; i < 4; i++) {
        int m = m0 + ty * 4 + i;
        #pragma unroll
        for (int j = 0; j < 4; j++) {
            int n = n0 + tx * 4 + j;
            out[(size_t)m * D_MODEL + n] = acc[i][j] + b[n];
        }
    }
}

// ---------------------------------------------------------------------------
// Zero the KV / ksum accumulators
// ---------------------------------------------------------------------------
__global__ void zero_kv()
{
    int i = blockIdx.x * blockDim.x + threadIdx.x;
    if (i < BH * DK * DK) g_kv[i] = 0.0f;
    if (i < BH * DK)      g_ksum[i] = 0.0f;
}

// ---------------------------------------------------------------------------
// KV reduction: per (b,h)  KV[d][e] = sum_s phi_k[s][d]*v[s][e];
//               ksum[d]    = sum_s phi_k[s][d]
// grid (BH, 16 chunks of 512 rows), 256 threads.
// thread t owns d0 = t/4, e range = (t%4)*16 .. +15  (16 accumulators)
// ---------------------------------------------------------------------------
__global__ __launch_bounds__(256)
void kv_kernel()
{
    const int bh = blockIdx.x;
    const int b = bh / NUM_HEADS, h = bh % NUM_HEADS;
    const int t = threadIdx.x;
    const int d0 = t >> 2;
    const int e0 = (t & 3) * 16;

    __shared__ float sk[8][64];
    __shared__ float sv[8][64];

    float acc[16] = {};
    float ksum = 0.0f;

    const size_t base = ((size_t)b * SEQ + (size_t)blockIdx.y * 512) * D_MODEL + h * DK;
    const int r0 = t / 64;          // 0..3
    const int c0 = t % 64;

    for (int s0 = 0; s0 < 512; s0 += 8) {
        // stage 8 rows of phi_k and v (head slice)
        sk[r0][c0]     = g_phi_k[base + (size_t)(s0 + r0) * D_MODEL + c0];
        sk[r0 + 4][c0] = g_phi_k[base + (size_t)(s0 + r0 + 4) * D_MODEL + c0];
        sv[r0][c0]     = g_vp[base + (size_t)(s0 + r0) * D_MODEL + c0];
        sv[r0 + 4][c0] = g_vp[base + (size_t)(s0 + r0 + 4) * D_MODEL + c0];
        __syncthreads();

        #pragma unroll
        for (int r = 0; r < 8; r++) {
            float kd = sk[r][d0];
            #pragma unroll
            for (int j = 0; j < 16; j++)
                acc[j] += kd * sv[r][e0 + j];
            if ((t & 3) == 0) ksum += kd;
        }
        __syncthreads();
    }

    float* kvp = &g_kv[(size_t)bh * DK * DK + d0 * DK + e0];
    #pragma unroll
    for (int j = 0; j < 16; j++)
        atomicAdd(&kvp[j], acc[j]);
    if ((t & 3) == 0)
        atomicAdd(&g_ksum[bh * DK + d0], ksum);
}

// ---------------------------------------------------------------------------
// Attention apply: attn[s][e] = (phi_q[s] . KV[:,e]) / (phi_q[s] . ksum + eps)
// grid (BH, 32 chunks of 256 rows), 256 threads (4 rows x 64 cols per iter)
// ---------------------------------------------------------------------------
__global__ __launch_bounds__(256)
void attn_kernel()
{
    const int bh = blockIdx.x;
    const int b = bh / NUM_HEADS, h = bh % NUM_HEADS;
    const int t = threadIdx.x;

    __shared__ float skv[64][64];
    __shared__ float sks[64];
    __shared__ float sq[4][64];

    // stage KV and ksum
    #pragma unroll
    for (int i = 0; i < 16; i++) {
        int idx = t + i * 256;
        skv[idx >> 6][idx & 63] = g_kv[(size_t)bh * DK * DK + idx];
    }
    if (t < 64) sks[t] = g_ksum[bh * DK + t];
    __syncthreads();

    const int rr = t / 64;     // row within 4-row group
    const int e  = t % 64;
    const size_t hbase = (size_t)b * SEQ * D_MODEL + h * DK;

    for (int s0 = blockIdx.y * 256; s0 < blockIdx.y * 256 + 256; s0 += 4) {
        sq[rr][e] = g_phi_q[hbase + (size_t)(s0 + rr) * D_MODEL + e];
        __syncthreads();

        float accn = 0.0f, accq = 0.0f;
        #pragma unroll
        for (int d = 0; d < 64; d++) {
            float qd = sq[rr][d];
            accn += qd * skv[d][e];
            accq += qd * sks[d];
        }
        g_attn[hbase + (size_t)(s0 + rr) * D_MODEL + e] = accn / (accq + 1e-6f);
        __syncthreads();
    }
}

// ---------------------------------------------------------------------------
extern "C" void kernel_launch(void* const* d_in, const int* in_sizes, int n_in,
                              void* d_out, int out_size)
{
    const float* query = (const float*)d_in[0];
    const float* key   = (const float*)d_in[1];
    const float* value = (const float*)d_in[2];
    const float* q_w1  = (const float*)d_in[3];
    const float* q_w2  = (const float*)d_in[4];
    const float* k_w1  = (const float*)d_in[5];
    const float* k_w2  = (const float*)d_in[6];
    const float* v_w1  = (const float*)d_in[7];
    const float* v_w2  = (const float*)d_in[8];
    const float* out_w = (const float*)d_in[9];
    const float* q_b1  = (const float*)d_in[10];
    const float* q_b2  = (const float*)d_in[11];
    const float* k_b1  = (const float*)d_in[12];
    const float* k_b2  = (const float*)d_in[13];
    const float* v_b1  = (const float*)d_in[14];
    const float* v_b2  = (const float*)d_in[15];
    const float* out_b = (const float*)d_in[16];
    float* out = (float*)d_out;

    // 1. fused gated projections (q,k,v) with phi applied to q,k
    {
        dim3 grid(D_MODEL / 64, M_TOTAL / 64, 3);
        dim3 block(16, 16);
        proj_gemm<<<grid, block>>>(query, key, value,
                                   q_w1, q_w2, k_w1, k_w2, v_w1, v_w2,
                                   q_b1, q_b2, k_b1, k_b2, v_b1, v_b2);
    }

    // 2. zero accumulators
    zero_kv<<<(BH * DK * DK + 255) / 256, 256>>>();

    // 3. KV / ksum reduction
    {
        dim3 grid(BH, SEQ / 512);
        kv_kernel<<<grid, 256>>>();
    }

    // 4. attention apply
    {
        dim3 grid(BH, SEQ / 256);
        attn_kernel<<<grid, 256>>>();
    }

    // 5. output projection
    {
        dim3 grid(D_MODEL / 64, M_TOTAL / 64);
        dim3 block(16, 16);
        final_gemm<<<grid, block>>>(out_w, out_b, out);
    }
}

// round 3
// speedup vs baseline: 1.8725x; 1.8725x over previous
#include <cuda_runtime.h>
#include <cuda_bf16.h>
#include <math.h>
#include <stdint.h>

#define D_MODEL 512
#define NUM_HEADS 8
#define DK 64
#define BATCH 4
#define SEQ 8192
#define M_TOTAL (BATCH * SEQ)
#define BH (BATCH * NUM_HEADS)

// ---------------- scratch -------------------------------------------------
__device__ float g_phi_q[M_TOTAL * D_MODEL];
__device__ float g_phi_k[M_TOTAL * D_MODEL];
__device__ float g_vp[M_TOTAL * D_MODEL];
__device__ float g_attn[M_TOTAL * D_MODEL];
__device__ float g_kv[BH * DK * DK];
__device__ float g_ksum[BH * DK];
__device__ __nv_bfloat16 g_whi[7 * D_MODEL * D_MODEL];
__device__ __nv_bfloat16 g_wlo[7 * D_MODEL * D_MODEL];

// ---------------- helpers -------------------------------------------------
__device__ __forceinline__ uint32_t smem_u32(const void* p) {
    uint32_t a;
    asm("{ .reg .u64 t; cvta.to.shared.u64 t, %1; cvt.u32.u64 %0, t; }"
        : "=r"(a) : "l"(p));
    return a;
}
__device__ __forceinline__ void cp_async16(uint32_t dst, const void* src) {
    asm volatile("cp.async.cg.shared.global [%0], [%1], 16;"
                 :: "r"(dst), "l"(src) : "memory");
}
__device__ __forceinline__ void ldm4(uint32_t* r, uint32_t addr) {
    asm volatile("ldmatrix.sync.aligned.m8n8.x4.shared.b16 {%0,%1,%2,%3}, [%4];"
                 : "=r"(r[0]), "=r"(r[1]), "=r"(r[2]), "=r"(r[3]) : "r"(addr));
}
__device__ __forceinline__ void mma16816(float* c, const uint32_t* a, const uint32_t* b) {
    asm volatile("mma.sync.aligned.m16n8k16.row.col.f32.bf16.bf16.f32 "
                 "{%0,%1,%2,%3}, {%4,%5,%6,%7}, {%8,%9}, {%0,%1,%2,%3};"
                 : "+f"(c[0]), "+f"(c[1]), "+f"(c[2]), "+f"(c[3])
                 : "r"(a[0]), "r"(a[1]), "r"(a[2]), "r"(a[3]),
                   "r"(b[0]), "r"(b[1]));
}
__device__ __forceinline__ void split2(float a, float b, uint32_t& hi, uint32_t& lo) {
    __nv_bfloat162 h = __floats2bfloat162_rn(a, b);
    float ra = a - __bfloat162float(h.x);
    float rb = b - __bfloat162float(h.y);
    __nv_bfloat162 l = __floats2bfloat162_rn(ra, rb);
    hi = *reinterpret_cast<uint32_t*>(&h);
    lo = *reinterpret_cast<uint32_t*>(&l);
}

// ---------------- weight split preconversion ------------------------------
__global__ __launch_bounds__(256)
void conv_w(const float* __restrict__ w0, const float* __restrict__ w1,
            const float* __restrict__ w2, const float* __restrict__ w3,
            const float* __restrict__ w4, const float* __restrict__ w5,
            const float* __restrict__ w6)
{
    int i = blockIdx.x * 256 + threadIdx.x;
    int m = i >> 18;
    int off = i & 262143;
    const float* w = (m == 0) ? w0 : (m == 1) ? w1 : (m == 2) ? w2 :
                     (m == 3) ? w3 : (m == 4) ? w4 : (m == 5) ? w5 : w6;
    float f = w[off];
    __nv_bfloat16 h = __float2bfloat16(f);
    g_whi[i] = h;
    g_wlo[i] = __float2bfloat16(f - __bfloat162float(h));
}

// ---------------- mma.sync GEMM (bf16x3, fused epilogue) ------------------
// mode 0/1/2: out = gate(x@w1^T+b1, x@w2^T+b2) [+ elu+1 for 0/1]; N strip 64
// mode 3:     out = g_attn @ out_w^T + out_b;                    N strip 128
// CTA: 256 threads, BM=128, BN(smem)=128, BK=32, warp tile 32x64.
#define AST   80                       // bytes per smem row (40 bf16)
#define AH_O  0
#define AL_O  10240
#define WH_O  20480
#define WL_O  30720
#define BUFB  40960
#define SMEM_SZ (2 * BUFB)

__global__ __launch_bounds__(256)
void mma_gemm(const float* __restrict__ x,
              const float* __restrict__ b1p, const float* __restrict__ b2p,
              float* __restrict__ out_final, int mode)
{
    extern __shared__ char smem[];
    const uint32_t sb = smem_u32(smem);
    const int tid = threadIdx.x;
    const int wid = tid >> 5;
    const int lid = tid & 31;
    const bool two_w = (mode < 3);

    const float* xs = (mode == 3) ? g_attn : x;
    float* op = (mode == 0) ? g_phi_q : (mode == 1) ? g_phi_k :
                (mode == 2) ? g_vp : out_final;

    const int m0 = blockIdx.y * 128;
    const int n0 = blockIdx.x * (two_w ? 64 : 128);
    const int rowB0 = two_w ? n0 : n0 + 64;

    const __nv_bfloat16* wAhi; const __nv_bfloat16* wAlo;
    const __nv_bfloat16* wBhi; const __nv_bfloat16* wBlo;
    if (two_w) {
        wAhi = g_whi + (size_t)(2 * mode) * 262144;
        wAlo = g_wlo + (size_t)(2 * mode) * 262144;
        wBhi = g_whi + (size_t)(2 * mode + 1) * 262144;
        wBlo = g_wlo + (size_t)(2 * mode + 1) * 262144;
    } else {
        wAhi = wBhi = g_whi + (size_t)6 * 262144;
        wAlo = wBlo = g_wlo + (size_t)6 * 262144;
    }

    const int wm = (wid & 3) * 32;      // warp M offset
    const int wn = (wid >> 2) * 64;     // warp N offset

    float acc[2][8][4];
    #pragma unroll
    for (int a = 0; a < 2; a++)
        #pragma unroll
        for (int b = 0; b < 8; b++)
            #pragma unroll
            for (int c = 0; c < 4; c++) acc[a][b][c] = 0.0f;

    float4 aPF[4];

    // ---- issue helpers (inlined by macro-ish lambdas) ----
    auto loadA = [&](int k0) {
        #pragma unroll
        for (int i = 0; i < 4; i++) {
            int idx = tid + i * 256;
            int row = idx >> 3;
            int kq  = (idx & 7) * 4;
            aPF[i] = *(const float4*)(xs + (size_t)(m0 + row) * D_MODEL + k0 + kq);
        }
    };
    auto stsA = [&](uint32_t bufo) {
        #pragma unroll
        for (int i = 0; i < 4; i++) {
            int idx = tid + i * 256;
            int row = idx >> 3;
            int kq  = (idx & 7) * 4;
            uint32_t h0, l0, h1, l1;
            split2(aPF[i].x, aPF[i].y, h0, l0);
            split2(aPF[i].z, aPF[i].w, h1, l1);
            uint32_t off = (uint32_t)(row * AST + kq * 2);
            *(uint2*)(smem + bufo + AH_O + off) = make_uint2(h0, h1);
            *(uint2*)(smem + bufo + AL_O + off) = make_uint2(l0, l1);
        }
    };
    auto issueW = [&](int k0, uint32_t bufo) {
        #pragma unroll
        for (int i = 0; i < 4; i++) {
            int idx = tid + i * 256;
            int half = idx >> 9;
            int r = (idx >> 2) & 127;
            int c16 = idx & 3;
            const __nv_bfloat16* wrow;
            if (r < 64)
                wrow = (half ? wAlo : wAhi) + (size_t)(n0 + r) * D_MODEL;
            else
                wrow = (half ? wBlo : wBhi) + (size_t)(rowB0 + r - 64) * D_MODEL;
            uint32_t dst = sb + bufo + WH_O + (uint32_t)half * (WL_O - WH_O)
                         + (uint32_t)(r * AST + c16 * 16);
            cp_async16(dst, wrow + k0 + c16 * 8);
        }
        asm volatile("cp.async.commit_group;" ::: "memory");
    };

    // ---- prologue ----
    loadA(0);
    issueW(0, 0);
    stsA(0);

    // ---- main K loop ----
    for (int c = 0; c < 16; c++) {
        const uint32_t bufc = (uint32_t)(c & 1) * BUFB;
        const uint32_t bufn = bufc ^ BUFB;
        if (c < 15) {
            loadA((c + 1) * 32);
            issueW((c + 1) * 32, bufn);
            asm volatile("cp.async.wait_group 1;" ::: "memory");
        } else {
            asm volatile("cp.async.wait_group 0;" ::: "memory");
        }
        __syncthreads();

        // compute on bufc
        #pragma unroll
        for (int kk = 0; kk < 32; kk += 16) {
            uint32_t ah[2][4], al[2][4];
            #pragma unroll
            for (int mt = 0; mt < 2; mt++) {
                uint32_t aoff = (uint32_t)((wm + mt * 16 + (lid & 15)) * AST
                               + (kk + ((lid >> 4) << 3)) * 2);
                ldm4(ah[mt], sb + bufc + AH_O + aoff);
                ldm4(al[mt], sb + bufc + AL_O + aoff);
            }
            uint32_t wh[8][2], wl[8][2];
            #pragma unroll
            for (int p = 0; p < 4; p++) {
                uint32_t woff = (uint32_t)((wn + (p * 2 + (lid >> 4)) * 8 + (lid & 7)) * AST
                               + (kk + (((lid >> 3) & 1) << 3)) * 2);
                ldm4(&wh[2 * p][0], sb + bufc + WH_O + woff);
                ldm4(&wl[2 * p][0], sb + bufc + WL_O + woff);
            }
            #pragma unroll
            for (int mt = 0; mt < 2; mt++)
                #pragma unroll
                for (int nt = 0; nt < 8; nt++)
                    mma16816(acc[mt][nt], ah[mt], wh[nt]);
            #pragma unroll
            for (int mt = 0; mt < 2; mt++)
                #pragma unroll
                for (int nt = 0; nt < 8; nt++)
                    mma16816(acc[mt][nt], ah[mt], wl[nt]);
            #pragma unroll
            for (int mt = 0; mt < 2; mt++)
                #pragma unroll
                for (int nt = 0; nt < 8; nt++)
                    mma16816(acc[mt][nt], al[mt], wh[nt]);
        }
        __syncthreads();
        if (c < 15) stsA(bufn);
    }

    // ---- epilogue: stage acc -> smem (reuse buffers) -> activate -> gmem --
    float* stg = (float*)smem;          // [128][132]
    #pragma unroll
    for (int mt = 0; mt < 2; mt++) {
        #pragma unroll
        for (int nt = 0; nt < 8; nt++) {
            int r = wm + mt * 16 + (lid >> 2);
            int cc = wn + nt * 8 + (lid & 3) * 2;
            *(float2*)&stg[r * 132 + cc]       = make_float2(acc[mt][nt][0], acc[mt][nt][1]);
            *(float2*)&stg[(r + 8) * 132 + cc] = make_float2(acc[mt][nt][2], acc[mt][nt][3]);
        }
    }
    __syncthreads();

    if (two_w) {
        #pragma unroll
        for (int i = 0; i < 32; i++) {
            int idx = tid + i * 256;
            int r = idx >> 6;
            int j = idx & 63;
            float a1 = stg[r * 132 + j]      + b1p[n0 + j];
            float a2 = stg[r * 132 + j + 64] + b2p[n0 + j];
            float s = a1 / (1.0f + expf(-a1));
            float p = s * a2;
            if (mode < 2) p = (p > 0.0f) ? (p + 1.0f) : expf(p);
            op[(size_t)(m0 + r) * D_MODEL + n0 + j] = p;
        }
    } else {
        #pragma unroll
        for (int i = 0; i < 64; i++) {
            int idx = tid + i * 256;
            int r = idx >> 7;
            int j = idx & 127;
            op[(size_t)(m0 + r) * D_MODEL + n0 + j] = stg[r * 132 + j] + b1p[n0 + j];
        }
    }
}

// ---------------- zero KV accumulators ------------------------------------
__global__ void zero_kv()
{
    int i = blockIdx.x * blockDim.x + threadIdx.x;
    if (i < BH * DK * DK) g_kv[i] = 0.0f;
    if (i < BH * DK)      g_ksum[i] = 0.0f;
}

// ---------------- KV reduction --------------------------------------------
__global__ __launch_bounds__(256)
void kv_kernel()
{
    const int bh = blockIdx.x;
    const int b = bh / NUM_HEADS, h = bh % NUM_HEADS;
    const int t = threadIdx.x;
    const int d0 = t >> 2;
    const int e0 = (t & 3) * 16;

    __shared__ float sk[8][64];
    __shared__ float sv[8][64];

    float acc[16] = {};
    float ksum = 0.0f;

    const size_t base = ((size_t)b * SEQ + (size_t)blockIdx.y * 512) * D_MODEL + h * DK;
    const int r0 = t / 64;
    const int c0 = t % 64;

    for (int s0 = 0; s0 < 512; s0 += 8) {
        sk[r0][c0]     = g_phi_k[base + (size_t)(s0 + r0) * D_MODEL + c0];
        sk[r0 + 4][c0] = g_phi_k[base + (size_t)(s0 + r0 + 4) * D_MODEL + c0];
        sv[r0][c0]     = g_vp[base + (size_t)(s0 + r0) * D_MODEL + c0];
        sv[r0 + 4][c0] = g_vp[base + (size_t)(s0 + r0 + 4) * D_MODEL + c0];
        __syncthreads();

        #pragma unroll
        for (int r = 0; r < 8; r++) {
            float kd = sk[r][d0];
            #pragma unroll
            for (int j = 0; j < 16; j++)
                acc[j] += kd * sv[r][e0 + j];
            if ((t & 3) == 0) ksum += kd;
        }
        __syncthreads();
    }

    float* kvp = &g_kv[(size_t)bh * DK * DK + d0 * DK + e0];
    #pragma unroll
    for (int j = 0; j < 16; j++)
        atomicAdd(&kvp[j], acc[j]);
    if ((t & 3) == 0)
        atomicAdd(&g_ksum[bh * DK + d0], ksum);
}

// ---------------- attention apply -----------------------------------------
__global__ __launch_bounds__(256)
void attn_kernel()
{
    const int bh = blockIdx.x;
    const int b = bh / NUM_HEADS, h = bh % NUM_HEADS;
    const int t = threadIdx.x;

    __shared__ float skv[64][64];
    __shared__ float sks[64];
    __shared__ float sq[4][64];

    #pragma unroll
    for (int i = 0; i < 16; i++) {
        int idx = t + i * 256;
        skv[idx >> 6][idx & 63] = g_kv[(size_t)bh * DK * DK + idx];
    }
    if (t < 64) sks[t] = g_ksum[bh * DK + t];
    __syncthreads();

    const int rr = t / 64;
    const int e  = t % 64;
    const size_t hbase = (size_t)b * SEQ * D_MODEL + h * DK;

    for (int s0 = blockIdx.y * 256; s0 < blockIdx.y * 256 + 256; s0 += 4) {
        sq[rr][e] = g_phi_q[hbase + (size_t)(s0 + rr) * D_MODEL + e];
        __syncthreads();

        float accn = 0.0f, accq = 0.0f;
        #pragma unroll
        for (int d = 0; d < 64; d++) {
            float qd = sq[rr][d];
            accn += qd * skv[d][e];
            accq += qd * sks[d];
        }
        g_attn[hbase + (size_t)(s0 + rr) * D_MODEL + e] = accn / (accq + 1e-6f);
        __syncthreads();
    }
}

// ---------------------------------------------------------------------------
extern "C" void kernel_launch(void* const* d_in, const int* in_sizes, int n_in,
                              void* d_out, int out_size)
{
    const float* query = (const float*)d_in[0];
    const float* key   = (const float*)d_in[1];
    const float* value = (const float*)d_in[2];
    const float* q_w1  = (const float*)d_in[3];
    const float* q_w2  = (const float*)d_in[4];
    const float* k_w1  = (const float*)d_in[5];
    const float* k_w2  = (const float*)d_in[6];
    const float* v_w1  = (const float*)d_in[7];
    const float* v_w2  = (const float*)d_in[8];
    const float* out_w = (const float*)d_in[9];
    const float* q_b1  = (const float*)d_in[10];
    const float* q_b2  = (const float*)d_in[11];
    const float* k_b1  = (const float*)d_in[12];
    const float* k_b2  = (const float*)d_in[13];
    const float* v_b1  = (const float*)d_in[14];
    const float* v_b2  = (const float*)d_in[15];
    const float* out_b = (const float*)d_in[16];
    float* out = (float*)d_out;

    cudaFuncSetAttribute(mma_gemm, cudaFuncAttributeMaxDynamicSharedMemorySize, SMEM_SZ);

    // 0. split weights to bf16 hi/lo
    conv_w<<<7 * D_MODEL * D_MODEL / 256, 256>>>(q_w1, q_w2, k_w1, k_w2, v_w1, v_w2, out_w);

    // 1. gated projections (tensor cores via mma.sync, bf16x3)
    dim3 pgrid(D_MODEL / 64, M_TOTAL / 128);
    mma_gemm<<<pgrid, 256, SMEM_SZ>>>(query, q_b1, q_b2, nullptr, 0);
    mma_gemm<<<pgrid, 256, SMEM_SZ>>>(key,   k_b1, k_b2, nullptr, 1);
    mma_gemm<<<pgrid, 256, SMEM_SZ>>>(value, v_b1, v_b2, nullptr, 2);

    // 2. linear attention
    zero_kv<<<(BH * DK * DK + 255) / 256, 256>>>();
    {
        dim3 grid(BH, SEQ / 512);
        kv_kernel<<<grid, 256>>>();
    }
    {
        dim3 grid(BH, SEQ / 256);
        attn_kernel<<<grid, 256>>>();
    }

    // 3. output projection
    dim3 fgrid(D_MODEL / 128, M_TOTAL / 128);
    mma_gemm<<<fgrid, 256, SMEM_SZ>>>(nullptr, out_b, out_b, out, 3);
}

// round 4
// speedup vs baseline: 2.2193x; 1.1852x over previous
#include <cuda_runtime.h>
#include <cuda_bf16.h>
#include <math.h>
#include <stdint.h>

#define D_MODEL 512
#define NUM_HEADS 8
#define DK 64
#define BATCH 4
#define SEQ 8192
#define M_TOTAL (BATCH * SEQ)
#define BH (BATCH * NUM_HEADS)

// ---------------- scratch -------------------------------------------------
__device__ float g_phi_q[M_TOTAL * D_MODEL];
__device__ float g_phi_k[M_TOTAL * D_MODEL];
__device__ float g_vp[M_TOTAL * D_MODEL];
__device__ float g_kv[BH * DK * DK];
__device__ float g_ksum[BH * DK];
__device__ __nv_bfloat16 g_whi[7 * D_MODEL * D_MODEL];
__device__ __nv_bfloat16 g_wlo[7 * D_MODEL * D_MODEL];
__device__ __nv_bfloat16 g_xhi[3 * M_TOTAL * D_MODEL];   // split q,k,v inputs
__device__ __nv_bfloat16 g_xlo[3 * M_TOTAL * D_MODEL];
__device__ __nv_bfloat16 g_ahi[M_TOTAL * D_MODEL];       // split attn output
__device__ __nv_bfloat16 g_alo[M_TOTAL * D_MODEL];

// ---------------- helpers -------------------------------------------------
__device__ __forceinline__ uint32_t smem_u32(const void* p) {
    uint32_t a;
    asm("{ .reg .u64 t; cvta.to.shared.u64 t, %1; cvt.u32.u64 %0, t; }"
        : "=r"(a) : "l"(p));
    return a;
}
__device__ __forceinline__ void cp_async16(uint32_t dst, const void* src) {
    asm volatile("cp.async.cg.shared.global [%0], [%1], 16;"
                 :: "r"(dst), "l"(src) : "memory");
}
__device__ __forceinline__ void ldm4(uint32_t* r, uint32_t addr) {
    asm volatile("ldmatrix.sync.aligned.m8n8.x4.shared.b16 {%0,%1,%2,%3}, [%4];"
                 : "=r"(r[0]), "=r"(r[1]), "=r"(r[2]), "=r"(r[3]) : "r"(addr));
}
__device__ __forceinline__ void mma16816(float* c, const uint32_t* a, const uint32_t* b) {
    asm volatile("mma.sync.aligned.m16n8k16.row.col.f32.bf16.bf16.f32 "
                 "{%0,%1,%2,%3}, {%4,%5,%6,%7}, {%8,%9}, {%0,%1,%2,%3};"
                 : "+f"(c[0]), "+f"(c[1]), "+f"(c[2]), "+f"(c[3])
                 : "r"(a[0]), "r"(a[1]), "r"(a[2]), "r"(a[3]),
                   "r"(b[0]), "r"(b[1]));
}
__device__ __forceinline__ void split2(float a, float b, uint32_t& hi, uint32_t& lo) {
    __nv_bfloat162 h = __floats2bfloat162_rn(a, b);
    float ra = a - __bfloat162float(h.x);
    float rb = b - __bfloat162float(h.y);
    __nv_bfloat162 l = __floats2bfloat162_rn(ra, rb);
    hi = *reinterpret_cast<uint32_t*>(&h);
    lo = *reinterpret_cast<uint32_t*>(&l);
}

// ---------------- weight split preconversion ------------------------------
__global__ __launch_bounds__(256)
void conv_w(const float* __restrict__ w0, const float* __restrict__ w1,
            const float* __restrict__ w2, const float* __restrict__ w3,
            const float* __restrict__ w4, const float* __restrict__ w5,
            const float* __restrict__ w6)
{
    int i = blockIdx.x * 256 + threadIdx.x;
    int m = i >> 18;
    int off = i & 262143;
    const float* w = (m == 0) ? w0 : (m == 1) ? w1 : (m == 2) ? w2 :
                     (m == 3) ? w3 : (m == 4) ? w4 : (m == 5) ? w5 : w6;
    float f = w[off];
    __nv_bfloat16 h = __float2bfloat16(f);
    g_whi[i] = h;
    g_wlo[i] = __float2bfloat16(f - __bfloat162float(h));
}

// ---------------- input split preconversion (float4 per thread) -----------
__global__ __launch_bounds__(256)
void conv_x(const float* __restrict__ q, const float* __restrict__ k,
            const float* __restrict__ v)
{
    size_t i4 = ((size_t)blockIdx.x * 256 + threadIdx.x) * 4;
    int m = (int)(i4 >> 24);
    size_t off = i4 & 0xFFFFFF;
    const float* s = (m == 0) ? q : (m == 1) ? k : v;
    float4 f = *(const float4*)(s + off);
    uint32_t h0, l0, h1, l1;
    split2(f.x, f.y, h0, l0);
    split2(f.z, f.w, h1, l1);
    *(uint2*)(g_xhi + i4) = make_uint2(h0, h1);
    *(uint2*)(g_xlo + i4) = make_uint2(l0, l1);
}

// ---------------- mma.sync GEMM (bf16x3, 3-stage cp.async) ----------------
// mode 0/1/2: out = gate(x@w1^T+b1, x@w2^T+b2) [+ elu+1 for 0/1]; N strip 64
// mode 3:     out = attn(bf16 split) @ out_w^T + out_b;          N strip 128
// Tiles: BM=128, BN(smem)=128, BK=32. Smem row = 128B: chunks 0-3 hi, 4-7 lo,
// SW128-style swizzle chunk' = chunk ^ (row & 7).
#define STAGE  32768
#define WOFF   16384
#define SMEM_SZ (3 * STAGE)

__global__ __launch_bounds__(256)
void mma_gemm(int mode, const float* __restrict__ b1p,
              const float* __restrict__ b2p, float* __restrict__ outf)
{
    extern __shared__ char smem[];
    const uint32_t sb = smem_u32(smem);
    const int tid = threadIdx.x;
    const int wid = tid >> 5;
    const int lid = tid & 31;
    const bool two_w = (mode < 3);

    const __nv_bfloat16* Ahi = two_w ? g_xhi + (size_t)mode * M_TOTAL * D_MODEL : g_ahi;
    const __nv_bfloat16* Alo = two_w ? g_xlo + (size_t)mode * M_TOTAL * D_MODEL : g_alo;
    float* op = (mode == 0) ? g_phi_q : (mode == 1) ? g_phi_k :
                (mode == 2) ? g_vp : outf;

    const int m0 = blockIdx.y * 128;
    const int n0 = blockIdx.x * (two_w ? 64 : 128);
    const int rowB0 = two_w ? n0 : n0 + 64;

    const __nv_bfloat16 *wAhi, *wAlo, *wBhi, *wBlo;
    if (two_w) {
        wAhi = g_whi + (size_t)(2 * mode) * 262144;
        wAlo = g_wlo + (size_t)(2 * mode) * 262144;
        wBhi = g_whi + (size_t)(2 * mode + 1) * 262144;
        wBlo = g_wlo + (size_t)(2 * mode + 1) * 262144;
    } else {
        wAhi = wBhi = g_whi + (size_t)6 * 262144;
        wAlo = wBlo = g_wlo + (size_t)6 * 262144;
    }

    const int wm = (wid & 3) * 32;
    const int wn = (wid >> 2) * 64;

    float acc[2][8][4];
    #pragma unroll
    for (int a = 0; a < 2; a++)
        #pragma unroll
        for (int b = 0; b < 8; b++)
            #pragma unroll
            for (int c = 0; c < 4; c++) acc[a][b][c] = 0.0f;

    auto issue = [&](int s) {
        const uint32_t bufo = (uint32_t)(s % 3) * STAGE;
        const int k0 = s * 32;
        #pragma unroll
        for (int i = 0; i < 8; i++) {
            int idx = tid + i * 256;
            int reg = idx >> 10;            // 0=A, 1=W
            int j = idx & 1023;
            int r = j >> 3;
            int c = j & 7;                  // 0-3 hi, 4-7 lo
            int cc = c & 3;
            const __nv_bfloat16* src;
            if (reg == 0) {
                src = ((c < 4) ? Ahi : Alo) + (size_t)(m0 + r) * D_MODEL + k0 + cc * 8;
            } else if (r < 64) {
                src = ((c < 4) ? wAhi : wAlo) + (size_t)(n0 + r) * D_MODEL + k0 + cc * 8;
            } else {
                src = ((c < 4) ? wBhi : wBlo) + (size_t)(rowB0 + r - 64) * D_MODEL + k0 + cc * 8;
            }
            uint32_t dst = sb + bufo + (uint32_t)reg * WOFF
                         + (uint32_t)(r * 128 + ((c ^ (r & 7)) * 16));
            cp_async16(dst, src);
        }
        asm volatile("cp.async.commit_group;" ::: "memory");
    };

    issue(0);
    issue(1);

    for (int c = 0; c < 16; c++) {
        if (c == 15) asm volatile("cp.async.wait_group 0;" ::: "memory");
        else         asm volatile("cp.async.wait_group 1;" ::: "memory");
        __syncthreads();

        const uint32_t bufc = sb + (uint32_t)(c % 3) * STAGE;
        #pragma unroll
        for (int kk = 0; kk < 32; kk += 16) {
            uint32_t ah[2][4], al[2][4];
            #pragma unroll
            for (int mt = 0; mt < 2; mt++) {
                int row = wm + mt * 16 + (lid & 15);
                int ch = (kk >> 3) + (lid >> 4);
                uint32_t base = bufc + (uint32_t)(row * 128);
                ldm4(ah[mt], base + (uint32_t)(((ch)     ^ (row & 7)) * 16));
                ldm4(al[mt], base + (uint32_t)(((ch + 4) ^ (row & 7)) * 16));
            }
            uint32_t wh[8][2], wl[8][2];
            #pragma unroll
            for (int p = 0; p < 4; p++) {
                int row = wn + (p * 2 + (lid >> 4)) * 8 + (lid & 7);
                int ch = (kk >> 3) + ((lid >> 3) & 1);
                uint32_t base = bufc + WOFF + (uint32_t)(row * 128);
                ldm4(&wh[2 * p][0], base + (uint32_t)(((ch)     ^ (row & 7)) * 16));
                ldm4(&wl[2 * p][0], base + (uint32_t)(((ch + 4) ^ (row & 7)) * 16));
            }
            #pragma unroll
            for (int mt = 0; mt < 2; mt++)
                #pragma unroll
                for (int nt = 0; nt < 8; nt++)
                    mma16816(acc[mt][nt], ah[mt], wh[nt]);
            #pragma unroll
            for (int mt = 0; mt < 2; mt++)
                #pragma unroll
                for (int nt = 0; nt < 8; nt++)
                    mma16816(acc[mt][nt], ah[mt], wl[nt]);
            #pragma unroll
            for (int mt = 0; mt < 2; mt++)
                #pragma unroll
                for (int nt = 0; nt < 8; nt++)
                    mma16816(acc[mt][nt], al[mt], wh[nt]);
        }
        if (c + 2 < 16) issue(c + 2);
    }
    __syncthreads();

    // ---- epilogue ----
    float* stg = (float*)smem;              // [128][132]
    #pragma unroll
    for (int mt = 0; mt < 2; mt++) {
        #pragma unroll
        for (int nt = 0; nt < 8; nt++) {
            int r = wm + mt * 16 + (lid >> 2);
            int cc = wn + nt * 8 + (lid & 3) * 2;
            *(float2*)&stg[r * 132 + cc]       = make_float2(acc[mt][nt][0], acc[mt][nt][1]);
            *(float2*)&stg[(r + 8) * 132 + cc] = make_float2(acc[mt][nt][2], acc[mt][nt][3]);
        }
    }
    __syncthreads();

    if (two_w) {
        #pragma unroll
        for (int i = 0; i < 32; i++) {
            int idx = tid + i * 256;
            int r = idx >> 6;
            int j = idx & 63;
            float a1 = stg[r * 132 + j]      + b1p[n0 + j];
            float a2 = stg[r * 132 + j + 64] + b2p[n0 + j];
            float s = a1 / (1.0f + expf(-a1));
            float p = s * a2;
            if (mode < 2) p = (p > 0.0f) ? (p + 1.0f) : expf(p);
            op[(size_t)(m0 + r) * D_MODEL + n0 + j] = p;
        }
    } else {
        #pragma unroll
        for (int i = 0; i < 64; i++) {
            int idx = tid + i * 256;
            int r = idx >> 7;
            int j = idx & 127;
            op[(size_t)(m0 + r) * D_MODEL + n0 + j] = stg[r * 132 + j] + b1p[n0 + j];
        }
    }
}

// ---------------- zero KV accumulators ------------------------------------
__global__ void zero_kv()
{
    int i = blockIdx.x * blockDim.x + threadIdx.x;
    if (i < BH * DK * DK) g_kv[i] = 0.0f;
    if (i < BH * DK)      g_ksum[i] = 0.0f;
}

// ---------------- KV reduction (float4 inner loads) ------------------------
__global__ __launch_bounds__(256)
void kv_kernel()
{
    const int bh = blockIdx.x;
    const int b = bh / NUM_HEADS, h = bh % NUM_HEADS;
    const int t = threadIdx.x;
    const int d0 = t >> 2;
    const int e0 = (t & 3) * 16;

    __shared__ float sk[8][64];
    __shared__ float sv[8][64];

    float acc[16] = {};
    float ksum = 0.0f;

    const size_t base = ((size_t)b * SEQ + (size_t)blockIdx.y * 512) * D_MODEL + h * DK;
    const int u = t & 127;
    const int lr = u >> 4;              // 0..7
    const int lc4 = (u & 15) * 4;

    for (int s0 = 0; s0 < 512; s0 += 8) {
        if (t < 128)
            *(float4*)&sk[lr][lc4] = *(const float4*)(g_phi_k + base + (size_t)(s0 + lr) * D_MODEL + lc4);
        else
            *(float4*)&sv[lr][lc4] = *(const float4*)(g_vp + base + (size_t)(s0 + lr) * D_MODEL + lc4);
        __syncthreads();

        #pragma unroll
        for (int r = 0; r < 8; r++) {
            float kd = sk[r][d0];
            const float4* vv = (const float4*)&sv[r][e0];
            float4 v0 = vv[0], v1 = vv[1], v2 = vv[2], v3 = vv[3];
            acc[0]  += kd * v0.x; acc[1]  += kd * v0.y; acc[2]  += kd * v0.z; acc[3]  += kd * v0.w;
            acc[4]  += kd * v1.x; acc[5]  += kd * v1.y; acc[6]  += kd * v1.z; acc[7]  += kd * v1.w;
            acc[8]  += kd * v2.x; acc[9]  += kd * v2.y; acc[10] += kd * v2.z; acc[11] += kd * v2.w;
            acc[12] += kd * v3.x; acc[13] += kd * v3.y; acc[14] += kd * v3.z; acc[15] += kd * v3.w;
            if ((t & 3) == 0) ksum += kd;
        }
        __syncthreads();
    }

    float* kvp = &g_kv[(size_t)bh * DK * DK + d0 * DK + e0];
    #pragma unroll
    for (int j = 0; j < 16; j++)
        atomicAdd(&kvp[j], acc[j]);
    if ((t & 3) == 0)
        atomicAdd(&g_ksum[bh * DK + d0], ksum);
}

// ---------------- attention apply (4x4 register tile) ----------------------
// block: 64 rows x 64 cols per (bh, chunk); writes split bf16 hi/lo.
__global__ __launch_bounds__(256)
void attn_kernel()
{
    __shared__ float skv[64][64];
    __shared__ float sqT[64][68];
    __shared__ float sks[64];

    const int bh = blockIdx.x;
    const int b = bh >> 3, h = bh & 7;
    const int t = threadIdx.x;

    #pragma unroll
    for (int i = 0; i < 4; i++) {
        int idx = t + i * 256;
        ((float4*)skv)[idx] = ((const float4*)(g_kv + (size_t)bh * 4096))[idx];
    }
    if (t < 64) sks[t] = g_ksum[bh * 64 + t];

    const int s0 = blockIdx.y * 64;
    const size_t hb = (size_t)b * SEQ * D_MODEL + (size_t)h * DK;
    {
        int r = t >> 2;
        int c0 = (t & 3) * 16;
        const float* src = g_phi_q + hb + (size_t)(s0 + r) * D_MODEL + c0;
        #pragma unroll
        for (int u = 0; u < 4; u++) {
            float4 v = *(const float4*)(src + u * 4);
            sqT[c0 + u * 4 + 0][r] = v.x;
            sqT[c0 + u * 4 + 1][r] = v.y;
            sqT[c0 + u * 4 + 2][r] = v.z;
            sqT[c0 + u * 4 + 3][r] = v.w;
        }
    }
    __syncthreads();

    const int tr = t >> 4, tc = t & 15;
    float accn[4][4];
    float accq[4] = {};
    #pragma unroll
    for (int i = 0; i < 4; i++)
        #pragma unroll
        for (int j = 0; j < 4; j++) accn[i][j] = 0.0f;

    #pragma unroll 8
    for (int d = 0; d < 64; d++) {
        float4 qv = *(float4*)&sqT[d][tr * 4];
        float4 kv = *(float4*)&skv[d][tc * 4];
        float ks = sks[d];
        float qa[4] = {qv.x, qv.y, qv.z, qv.w};
        float ka[4] = {kv.x, kv.y, kv.z, kv.w};
        #pragma unroll
        for (int i = 0; i < 4; i++) {
            accq[i] += qa[i] * ks;
            #pragma unroll
            for (int j = 0; j < 4; j++)
                accn[i][j] += qa[i] * ka[j];
        }
    }

    #pragma unroll
    for (int i = 0; i < 4; i++) {
        float den = accq[i] + 1e-6f;
        float o[4];
        #pragma unroll
        for (int j = 0; j < 4; j++) o[j] = accn[i][j] / den;
        uint32_t h0, l0, h1, l1;
        split2(o[0], o[1], h0, l0);
        split2(o[2], o[3], h1, l1);
        size_t orow = ((size_t)b * SEQ + s0 + tr * 4 + i) * D_MODEL + h * DK + tc * 4;
        *(uint2*)(g_ahi + orow) = make_uint2(h0, h1);
        *(uint2*)(g_alo + orow) = make_uint2(l0, l1);
    }
}

// ---------------------------------------------------------------------------
extern "C" void kernel_launch(void* const* d_in, const int* in_sizes, int n_in,
                              void* d_out, int out_size)
{
    const float* query = (const float*)d_in[0];
    const float* key   = (const float*)d_in[1];
    const float* value = (const float*)d_in[2];
    const float* q_w1  = (const float*)d_in[3];
    const float* q_w2  = (const float*)d_in[4];
    const float* k_w1  = (const float*)d_in[5];
    const float* k_w2  = (const float*)d_in[6];
    const float* v_w1  = (const float*)d_in[7];
    const float* v_w2  = (const float*)d_in[8];
    const float* out_w = (const float*)d_in[9];
    const float* q_b1  = (const float*)d_in[10];
    const float* q_b2  = (const float*)d_in[11];
    const float* k_b1  = (const float*)d_in[12];
    const float* k_b2  = (const float*)d_in[13];
    const float* v_b1  = (const float*)d_in[14];
    const float* v_b2  = (const float*)d_in[15];
    const float* out_b = (const float*)d_in[16];
    float* out = (float*)d_out;

    cudaFuncSetAttribute(mma_gemm, cudaFuncAttributeMaxDynamicSharedMemorySize, SMEM_SZ);

    // 0. split weights + inputs to bf16 hi/lo
    conv_w<<<7 * D_MODEL * D_MODEL / 256, 256>>>(q_w1, q_w2, k_w1, k_w2, v_w1, v_w2, out_w);
    conv_x<<<3 * M_TOTAL * D_MODEL / (256 * 4), 256>>>(query, key, value);

    // 1. gated projections
    dim3 pgrid(D_MODEL / 64, M_TOTAL / 128);
    mma_gemm<<<pgrid, 256, SMEM_SZ>>>(0, q_b1, q_b2, nullptr);
    mma_gemm<<<pgrid, 256, SMEM_SZ>>>(1, k_b1, k_b2, nullptr);
    mma_gemm<<<pgrid, 256, SMEM_SZ>>>(2, v_b1, v_b2, nullptr);

    // 2. linear attention
    zero_kv<<<(BH * DK * DK + 255) / 256, 256>>>();
    {
        dim3 grid(BH, SEQ / 512);
        kv_kernel<<<grid, 256>>>();
    }
    {
        dim3 grid(BH, SEQ / 64);
        attn_kernel<<<grid, 256>>>();
    }

    // 3. output projection
    dim3 fgrid(D_MODEL / 128, M_TOTAL / 128);
    mma_gemm<<<fgrid, 256, SMEM_SZ>>>(3, out_b, out_b, out);
}

// round 5
// speedup vs baseline: 2.6427x; 1.1908x over previous
#include <cuda_runtime.h>
#include <cuda_bf16.h>
#include <math.h>
#include <stdint.h>

#define D_MODEL 512
#define NUM_HEADS 8
#define DK 64
#define BATCH 4
#define SEQ 8192
#define M_TOTAL (BATCH * SEQ)
#define BH (BATCH * NUM_HEADS)

// ---------------- scratch -------------------------------------------------
__device__ float g_phi_q[M_TOTAL * D_MODEL];
__device__ float g_phi_k[M_TOTAL * D_MODEL];
__device__ float g_vp[M_TOTAL * D_MODEL];
__device__ float g_kv[BH * DK * DK];
__device__ float g_ksum[BH * DK];
__device__ __nv_bfloat16 g_whi[7 * D_MODEL * D_MODEL];
__device__ __nv_bfloat16 g_wlo[7 * D_MODEL * D_MODEL];
__device__ __nv_bfloat16 g_xhi[3 * M_TOTAL * D_MODEL];   // split q,k,v inputs
__device__ __nv_bfloat16 g_xlo[3 * M_TOTAL * D_MODEL];
__device__ __nv_bfloat16 g_ahi[M_TOTAL * D_MODEL];       // split attn output
__device__ __nv_bfloat16 g_alo[M_TOTAL * D_MODEL];

// ---------------- helpers -------------------------------------------------
__device__ __forceinline__ uint32_t smem_u32(const void* p) {
    uint32_t a;
    asm("{ .reg .u64 t; cvta.to.shared.u64 t, %1; cvt.u32.u64 %0, t; }"
        : "=r"(a) : "l"(p));
    return a;
}
__device__ __forceinline__ void cp_async16(uint32_t dst, const void* src) {
    asm volatile("cp.async.cg.shared.global [%0], [%1], 16;"
                 :: "r"(dst), "l"(src) : "memory");
}
__device__ __forceinline__ void ldm4(uint32_t* r, uint32_t addr) {
    asm volatile("ldmatrix.sync.aligned.m8n8.x4.shared.b16 {%0,%1,%2,%3}, [%4];"
                 : "=r"(r[0]), "=r"(r[1]), "=r"(r[2]), "=r"(r[3]) : "r"(addr));
}
__device__ __forceinline__ void mma16816(float* c, const uint32_t* a, const uint32_t* b) {
    asm volatile("mma.sync.aligned.m16n8k16.row.col.f32.bf16.bf16.f32 "
                 "{%0,%1,%2,%3}, {%4,%5,%6,%7}, {%8,%9}, {%0,%1,%2,%3};"
                 : "+f"(c[0]), "+f"(c[1]), "+f"(c[2]), "+f"(c[3])
                 : "r"(a[0]), "r"(a[1]), "r"(a[2]), "r"(a[3]),
                   "r"(b[0]), "r"(b[1]));
}
__device__ __forceinline__ void split2(float a, float b, uint32_t& hi, uint32_t& lo) {
    __nv_bfloat162 h = __floats2bfloat162_rn(a, b);
    float ra = a - __bfloat162float(h.x);
    float rb = b - __bfloat162float(h.y);
    __nv_bfloat162 l = __floats2bfloat162_rn(ra, rb);
    hi = *reinterpret_cast<uint32_t*>(&h);
    lo = *reinterpret_cast<uint32_t*>(&l);
}

// ---------------- weight split preconversion ------------------------------
__global__ __launch_bounds__(256)
void conv_w(const float* __restrict__ w0, const float* __restrict__ w1,
            const float* __restrict__ w2, const float* __restrict__ w3,
            const float* __restrict__ w4, const float* __restrict__ w5,
            const float* __restrict__ w6)
{
    int i = blockIdx.x * 256 + threadIdx.x;
    int m = i >> 18;
    int off = i & 262143;
    const float* w = (m == 0) ? w0 : (m == 1) ? w1 : (m == 2) ? w2 :
                     (m == 3) ? w3 : (m == 4) ? w4 : (m == 5) ? w5 : w6;
    float f = w[off];
    __nv_bfloat16 h = __float2bfloat16(f);
    g_whi[i] = h;
    g_wlo[i] = __float2bfloat16(f - __bfloat162float(h));
}

// ---------------- input split preconversion (float4 per thread) -----------
__global__ __launch_bounds__(256)
void conv_x(const float* __restrict__ q, const float* __restrict__ k,
            const float* __restrict__ v)
{
    size_t i4 = ((size_t)blockIdx.x * 256 + threadIdx.x) * 4;
    int m = (int)(i4 >> 24);
    size_t off = i4 & 0xFFFFFF;
    const float* s = (m == 0) ? q : (m == 1) ? k : v;
    float4 f = *(const float4*)(s + off);
    uint32_t h0, l0, h1, l1;
    split2(f.x, f.y, h0, l0);
    split2(f.z, f.w, h1, l1);
    *(uint2*)(g_xhi + i4) = make_uint2(h0, h1);
    *(uint2*)(g_xlo + i4) = make_uint2(l0, l1);
}

// ---------------- mma.sync GEMM (bf16x3, 3-stage cp.async, 2 CTA/SM) ------
// mode 0/1/2: out = gate(x@w1^T+b1, x@w2^T+b2) [+ elu+1 for 0/1]; N strip 64
// mode 3:     out = attn(bf16 split) @ out_w^T + out_b;          N strip 128
// Tiles: BM=128, BN(smem)=128, BK=32. Smem row = 128B: chunks 0-3 hi, 4-7 lo,
// swizzle chunk' = chunk ^ (row & 7). W fragments streamed in 2 groups of 4
// N-tiles to keep live registers <= 128 (2 CTAs/SM).
#define STAGE  32768
#define WOFF   16384
#define SMEM_SZ (3 * STAGE)

__global__ __launch_bounds__(256, 2)
void mma_gemm(int mode, const float* __restrict__ b1p,
              const float* __restrict__ b2p, float* __restrict__ outf)
{
    extern __shared__ char smem[];
    const uint32_t sb = smem_u32(smem);
    const int tid = threadIdx.x;
    const int wid = tid >> 5;
    const int lid = tid & 31;
    const bool two_w = (mode < 3);

    const __nv_bfloat16* Ahi = two_w ? g_xhi + (size_t)mode * M_TOTAL * D_MODEL : g_ahi;
    const __nv_bfloat16* Alo = two_w ? g_xlo + (size_t)mode * M_TOTAL * D_MODEL : g_alo;
    float* op = (mode == 0) ? g_phi_q : (mode == 1) ? g_phi_k :
                (mode == 2) ? g_vp : outf;

    const int m0 = blockIdx.y * 128;
    const int n0 = blockIdx.x * (two_w ? 64 : 128);
    const int rowB0 = two_w ? n0 : n0 + 64;

    const __nv_bfloat16 *wAhi, *wAlo, *wBhi, *wBlo;
    if (two_w) {
        wAhi = g_whi + (size_t)(2 * mode) * 262144;
        wAlo = g_wlo + (size_t)(2 * mode) * 262144;
        wBhi = g_whi + (size_t)(2 * mode + 1) * 262144;
        wBlo = g_wlo + (size_t)(2 * mode + 1) * 262144;
    } else {
        wAhi = wBhi = g_whi + (size_t)6 * 262144;
        wAlo = wBlo = g_wlo + (size_t)6 * 262144;
    }

    const int wm = (wid & 3) * 32;
    const int wn = (wid >> 2) * 64;

    // hoisted per-warp smem offsets (within a stage)
    const uint32_t aRow0 = (uint32_t)(wm + (lid & 15));        // + mt*16
    const uint32_t aChSel = (uint32_t)(lid >> 4);              // 0/1
    const uint32_t wRowBase = (uint32_t)(wn + (lid >> 4) * 8 + (lid & 7)); // + grp*32 + p*16
    const uint32_t wChSel = (uint32_t)((lid >> 3) & 1);

    float acc[2][8][4];
    #pragma unroll
    for (int a = 0; a < 2; a++)
        #pragma unroll
        for (int b = 0; b < 8; b++)
            #pragma unroll
            for (int c = 0; c < 4; c++) acc[a][b][c] = 0.0f;

    auto issue = [&](int s) {
        const uint32_t bufo = (uint32_t)(s % 3) * STAGE;
        const int k0 = s * 32;
        #pragma unroll
        for (int i = 0; i < 8; i++) {
            int idx = tid + i * 256;
            int reg = idx >> 10;            // 0=A, 1=W
            int j = idx & 1023;
            int r = j >> 3;
            int c = j & 7;                  // 0-3 hi, 4-7 lo
            int cc = c & 3;
            const __nv_bfloat16* src;
            if (reg == 0) {
                src = ((c < 4) ? Ahi : Alo) + (size_t)(m0 + r) * D_MODEL + k0 + cc * 8;
            } else if (r < 64) {
                src = ((c < 4) ? wAhi : wAlo) + (size_t)(n0 + r) * D_MODEL + k0 + cc * 8;
            } else {
                src = ((c < 4) ? wBhi : wBlo) + (size_t)(rowB0 + r - 64) * D_MODEL + k0 + cc * 8;
            }
            uint32_t dst = sb + bufo + (uint32_t)reg * WOFF
                         + (uint32_t)(r * 128 + ((c ^ (r & 7)) * 16));
            cp_async16(dst, src);
        }
        asm volatile("cp.async.commit_group;" ::: "memory");
    };

    issue(0);
    issue(1);

    for (int c = 0; c < 16; c++) {
        if (c == 15) asm volatile("cp.async.wait_group 0;" ::: "memory");
        else         asm volatile("cp.async.wait_group 1;" ::: "memory");
        __syncthreads();

        const uint32_t bufc = sb + (uint32_t)(c % 3) * STAGE;
        #pragma unroll
        for (int kk = 0; kk < 32; kk += 16) {
            uint32_t ah[2][4], al[2][4];
            #pragma unroll
            for (int mt = 0; mt < 2; mt++) {
                uint32_t row = aRow0 + (uint32_t)(mt * 16);
                uint32_t ch = (uint32_t)(kk >> 3) + aChSel;
                uint32_t base = bufc + row * 128;
                ldm4(ah[mt], base + (((ch)     ^ (row & 7)) * 16));
                ldm4(al[mt], base + (((ch + 4) ^ (row & 7)) * 16));
            }
            #pragma unroll
            for (int grp = 0; grp < 2; grp++) {      // 4 N-tiles per group
                uint32_t wh[4][2], wl[4][2];
                #pragma unroll
                for (int p = 0; p < 2; p++) {
                    uint32_t row = wRowBase + (uint32_t)(grp * 32 + p * 16);
                    uint32_t ch = (uint32_t)(kk >> 3) + wChSel;
                    uint32_t base = bufc + WOFF + row * 128;
                    ldm4(&wh[2 * p][0], base + (((ch)     ^ (row & 7)) * 16));
                    ldm4(&wl[2 * p][0], base + (((ch + 4) ^ (row & 7)) * 16));
                }
                #pragma unroll
                for (int mt = 0; mt < 2; mt++)
                    #pragma unroll
                    for (int nt = 0; nt < 4; nt++)
                        mma16816(acc[mt][grp * 4 + nt], ah[mt], wh[nt]);
                #pragma unroll
                for (int mt = 0; mt < 2; mt++)
                    #pragma unroll
                    for (int nt = 0; nt < 4; nt++)
                        mma16816(acc[mt][grp * 4 + nt], ah[mt], wl[nt]);
                #pragma unroll
                for (int mt = 0; mt < 2; mt++)
                    #pragma unroll
                    for (int nt = 0; nt < 4; nt++)
                        mma16816(acc[mt][grp * 4 + nt], al[mt], wh[nt]);
            }
        }
        if (c + 2 < 16) issue(c + 2);
    }
    __syncthreads();

    // ---- epilogue ----
    float* stg = (float*)smem;              // [128][132]
    #pragma unroll
    for (int mt = 0; mt < 2; mt++) {
        #pragma unroll
        for (int nt = 0; nt < 8; nt++) {
            int r = wm + mt * 16 + (lid >> 2);
            int cc = wn + nt * 8 + (lid & 3) * 2;
            *(float2*)&stg[r * 132 + cc]       = make_float2(acc[mt][nt][0], acc[mt][nt][1]);
            *(float2*)&stg[(r + 8) * 132 + cc] = make_float2(acc[mt][nt][2], acc[mt][nt][3]);
        }
    }
    __syncthreads();

    if (two_w) {
        #pragma unroll
        for (int i = 0; i < 32; i++) {
            int idx = tid + i * 256;
            int r = idx >> 6;
            int j = idx & 63;
            float a1 = stg[r * 132 + j]      + b1p[n0 + j];
            float a2 = stg[r * 132 + j + 64] + b2p[n0 + j];
            float s = a1 / (1.0f + expf(-a1));
            float p = s * a2;
            if (mode < 2) p = (p > 0.0f) ? (p + 1.0f) : expf(p);
            op[(size_t)(m0 + r) * D_MODEL + n0 + j] = p;
        }
    } else {
        #pragma unroll
        for (int i = 0; i < 64; i++) {
            int idx = tid + i * 256;
            int r = idx >> 7;
            int j = idx & 127;
            op[(size_t)(m0 + r) * D_MODEL + n0 + j] = stg[r * 132 + j] + b1p[n0 + j];
        }
    }
}

// ---------------- zero KV accumulators ------------------------------------
__global__ void zero_kv()
{
    int i = blockIdx.x * blockDim.x + threadIdx.x;
    if (i < BH * DK * DK) g_kv[i] = 0.0f;
    if (i < BH * DK)      g_ksum[i] = 0.0f;
}

// ---------------- KV reduction (float4 inner loads) ------------------------
__global__ __launch_bounds__(256)
void kv_kernel()
{
    const int bh = blockIdx.x;
    const int b = bh / NUM_HEADS, h = bh % NUM_HEADS;
    const int t = threadIdx.x;
    const int d0 = t >> 2;
    const int e0 = (t & 3) * 16;

    __shared__ float sk[8][64];
    __shared__ float sv[8][64];

    float acc[16] = {};
    float ksum = 0.0f;

    const size_t base = ((size_t)b * SEQ + (size_t)blockIdx.y * 512) * D_MODEL + h * DK;
    const int u = t & 127;
    const int lr = u >> 4;
    const int lc4 = (u & 15) * 4;

    for (int s0 = 0; s0 < 512; s0 += 8) {
        if (t < 128)
            *(float4*)&sk[lr][lc4] = *(const float4*)(g_phi_k + base + (size_t)(s0 + lr) * D_MODEL + lc4);
        else
            *(float4*)&sv[lr][lc4] = *(const float4*)(g_vp + base + (size_t)(s0 + lr) * D_MODEL + lc4);
        __syncthreads();

        #pragma unroll
        for (int r = 0; r < 8; r++) {
            float kd = sk[r][d0];
            const float4* vv = (const float4*)&sv[r][e0];
            float4 v0 = vv[0], v1 = vv[1], v2 = vv[2], v3 = vv[3];
            acc[0]  += kd * v0.x; acc[1]  += kd * v0.y; acc[2]  += kd * v0.z; acc[3]  += kd * v0.w;
            acc[4]  += kd * v1.x; acc[5]  += kd * v1.y; acc[6]  += kd * v1.z; acc[7]  += kd * v1.w;
            acc[8]  += kd * v2.x; acc[9]  += kd * v2.y; acc[10] += kd * v2.z; acc[11] += kd * v2.w;
            acc[12] += kd * v3.x; acc[13] += kd * v3.y; acc[14] += kd * v3.z; acc[15] += kd * v3.w;
            if ((t & 3) == 0) ksum += kd;
        }
        __syncthreads();
    }

    float* kvp = &g_kv[(size_t)bh * DK * DK + d0 * DK + e0];
    #pragma unroll
    for (int j = 0; j < 16; j++)
        atomicAdd(&kvp[j], acc[j]);
    if ((t & 3) == 0)
        atomicAdd(&g_ksum[bh * DK + d0], ksum);
}

// ---------------- attention apply (4x4 register tile) ----------------------
__global__ __launch_bounds__(256)
void attn_kernel()
{
    __shared__ float skv[64][64];
    __shared__ float sqT[64][68];
    __shared__ float sks[64];

    const int bh = blockIdx.x;
    const int b = bh >> 3, h = bh & 7;
    const int t = threadIdx.x;

    #pragma unroll
    for (int i = 0; i < 4; i++) {
        int idx = t + i * 256;
        ((float4*)skv)[idx] = ((const float4*)(g_kv + (size_t)bh * 4096))[idx];
    }
    if (t < 64) sks[t] = g_ksum[bh * 64 + t];

    const int s0 = blockIdx.y * 64;
    const size_t hb = (size_t)b * SEQ * D_MODEL + (size_t)h * DK;
    {
        int r = t >> 2;
        int c0 = (t & 3) * 16;
        const float* src = g_phi_q + hb + (size_t)(s0 + r) * D_MODEL + c0;
        #pragma unroll
        for (int u = 0; u < 4; u++) {
            float4 v = *(const float4*)(src + u * 4);
            sqT[c0 + u * 4 + 0][r] = v.x;
            sqT[c0 + u * 4 + 1][r] = v.y;
            sqT[c0 + u * 4 + 2][r] = v.z;
            sqT[c0 + u * 4 + 3][r] = v.w;
        }
    }
    __syncthreads();

    const int tr = t >> 4, tc = t & 15;
    float accn[4][4];
    float accq[4] = {};
    #pragma unroll
    for (int i = 0; i < 4; i++)
        #pragma unroll
        for (int j = 0; j < 4; j++) accn[i][j] = 0.0f;

    #pragma unroll 8
    for (int d = 0; d < 64; d++) {
        float4 qv = *(float4*)&sqT[d][tr * 4];
        float4 kv = *(float4*)&skv[d][tc * 4];
        float ks = sks[d];
        float qa[4] = {qv.x, qv.y, qv.z, qv.w};
        float ka[4] = {kv.x, kv.y, kv.z, kv.w};
        #pragma unroll
        for (int i = 0; i < 4; i++) {
            accq[i] += qa[i] * ks;
            #pragma unroll
            for (int j = 0; j < 4; j++)
                accn[i][j] += qa[i] * ka[j];
        }
    }

    #pragma unroll
    for (int i = 0; i < 4; i++) {
        float den = accq[i] + 1e-6f;
        float o[4];
        #pragma unroll
        for (int j = 0; j < 4; j++) o[j] = accn[i][j] / den;
        uint32_t h0, l0, h1, l1;
        split2(o[0], o[1], h0, l0);
        split2(o[2], o[3], h1, l1);
        size_t orow = ((size_t)b * SEQ + s0 + tr * 4 + i) * D_MODEL + h * DK + tc * 4;
        *(uint2*)(g_ahi + orow) = make_uint2(h0, h1);
        *(uint2*)(g_alo + orow) = make_uint2(l0, l1);
    }
}

// ---------------------------------------------------------------------------
extern "C" void kernel_launch(void* const* d_in, const int* in_sizes, int n_in,
                              void* d_out, int out_size)
{
    const float* query = (const float*)d_in[0];
    const float* key   = (const float*)d_in[1];
    const float* value = (const float*)d_in[2];
    const float* q_w1  = (const float*)d_in[3];
    const float* q_w2  = (const float*)d_in[4];
    const float* k_w1  = (const float*)d_in[5];
    const float* k_w2  = (const float*)d_in[6];
    const float* v_w1  = (const float*)d_in[7];
    const float* v_w2  = (const float*)d_in[8];
    const float* out_w = (const float*)d_in[9];
    const float* q_b1  = (const float*)d_in[10];
    const float* q_b2  = (const float*)d_in[11];
    const float* k_b1  = (const float*)d_in[12];
    const float* k_b2  = (const float*)d_in[13];
    const float* v_b1  = (const float*)d_in[14];
    const float* v_b2  = (const float*)d_in[15];
    const float* out_b = (const float*)d_in[16];
    float* out = (float*)d_out;

    cudaFuncSetAttribute(mma_gemm, cudaFuncAttributeMaxDynamicSharedMemorySize, SMEM_SZ);

    // 0. split weights + inputs to bf16 hi/lo
    conv_w<<<7 * D_MODEL * D_MODEL / 256, 256>>>(q_w1, q_w2, k_w1, k_w2, v_w1, v_w2, out_w);
    conv_x<<<3 * M_TOTAL * D_MODEL / (256 * 4), 256>>>(query, key, value);

    // 1. gated projections
    dim3 pgrid(D_MODEL / 64, M_TOTAL / 128);
    mma_gemm<<<pgrid, 256, SMEM_SZ>>>(0, q_b1, q_b2, nullptr);
    mma_gemm<<<pgrid, 256, SMEM_SZ>>>(1, k_b1, k_b2, nullptr);
    mma_gemm<<<pgrid, 256, SMEM_SZ>>>(2, v_b1, v_b2, nullptr);

    // 2. linear attention
    zero_kv<<<(BH * DK * DK + 255) / 256, 256>>>();
    {
        dim3 grid(BH, SEQ / 512);
        kv_kernel<<<grid, 256>>>();
    }
    {
        dim3 grid(BH, SEQ / 64);
        attn_kernel<<<grid, 256>>>();
    }

    // 3. output projection
    dim3 fgrid(D_MODEL / 128, M_TOTAL / 128);
    mma_gemm<<<fgrid, 256, SMEM_SZ>>>(3, out_b, out_b, out);
}